// round 2
// baseline (speedup 1.0000x reference)
#include <cuda_runtime.h>
#include <math_constants.h>
#include <cstdint>

// Problem constants
#define BB 2
#define SS 2048
#define EE 1024
#define HH 16
#define DD 64
// M rows for projections = B*S = 4096

// Scratch (device globals — allocation-free rule)
__device__ float g_q[BB * SS * EE];
__device__ float g_k[BB * SS * EE];
__device__ float g_v[BB * SS * EE];
__device__ float g_ctx[BB * SS * EE];

// ---------------------------------------------------------------------------
// Tiled SGEMM: C[M,N] = A[M,K] @ W[K,N] + bias[N]
// 64x64 block tile, BK=16, 256 threads, 4x4 per-thread microtile.
// ---------------------------------------------------------------------------
__global__ __launch_bounds__(256) void sgemm64(
    const float* __restrict__ A, const float* __restrict__ W,
    const float* __restrict__ bias, float* __restrict__ C,
    int M, int N, int K)
{
    __shared__ float As[16][68];  // transposed: As[k][m]
    __shared__ float Bs[16][68];  // Bs[k][n]

    const int tid = threadIdx.x;
    const int tx = tid & 15;
    const int ty = tid >> 4;
    const int m0 = blockIdx.y * 64;
    const int n0 = blockIdx.x * 64;

    // load assignments
    const int lm  = tid >> 2;          // 0..63 (A row)
    const int lk4 = (tid & 3) * 4;     // 0,4,8,12 (A k offset)
    const int lbk = tid >> 4;          // 0..15 (W k row)
    const int lbn = (tid & 15) * 4;    // 0..60 (W n offset)

    float acc[4][4] = {};

    for (int k0 = 0; k0 < K; k0 += 16) {
        float4 a4 = *(const float4*)&A[(size_t)(m0 + lm) * K + k0 + lk4];
        As[lk4 + 0][lm] = a4.x;
        As[lk4 + 1][lm] = a4.y;
        As[lk4 + 2][lm] = a4.z;
        As[lk4 + 3][lm] = a4.w;
        *(float4*)&Bs[lbk][lbn] =
            *(const float4*)&W[(size_t)(k0 + lbk) * N + n0 + lbn];
        __syncthreads();

        #pragma unroll
        for (int kk = 0; kk < 16; kk++) {
            float4 av = *(const float4*)&As[kk][ty * 4];
            float4 bv = *(const float4*)&Bs[kk][tx * 4];
            float a[4] = {av.x, av.y, av.z, av.w};
            float b[4] = {bv.x, bv.y, bv.z, bv.w};
            #pragma unroll
            for (int i = 0; i < 4; i++)
                #pragma unroll
                for (int j = 0; j < 4; j++)
                    acc[i][j] = fmaf(a[i], b[j], acc[i][j]);
        }
        __syncthreads();
    }

    float4 bv = *(const float4*)&bias[n0 + tx * 4];
    float bb[4] = {bv.x, bv.y, bv.z, bv.w};
    #pragma unroll
    for (int i = 0; i < 4; i++) {
        int row = m0 + ty * 4 + i;
        float4 o;
        o.x = acc[i][0] + bb[0];
        o.y = acc[i][1] + bb[1];
        o.z = acc[i][2] + bb[2];
        o.w = acc[i][3] + bb[3];
        *(float4*)&C[(size_t)row * N + n0 + tx * 4] = o;
    }
}

// ---------------------------------------------------------------------------
// Flash attention (causal). Q/K/V stored as [B, S, H*D] fp32.
// One block = 64 query rows of one (b, h). 256 threads, 4x4 microtiles.
// Dynamic smem: Qt[64][68] (d-major), KtP[64][68] (K^T then reused as P^T),
// Vs[64][68] (k-major). 52224 bytes.
// ---------------------------------------------------------------------------
__global__ __launch_bounds__(256) void flash_attn(
    const float* __restrict__ Qg, const float* __restrict__ Kg,
    const float* __restrict__ Vg, float* __restrict__ ctx)
{
    extern __shared__ float sm[];
    float (*Qt)[68]  = (float(*)[68])sm;               // Qt[d][r]
    float (*KtP)[68] = (float(*)[68])(sm + 64 * 68);   // Kt[d][c] / Ps[c][r]
    float (*Vs)[68]  = (float(*)[68])(sm + 2 * 64 * 68); // Vs[c][d]

    const int tid = threadIdx.x;
    const int tx = tid & 15;
    const int ty = tid >> 4;
    const int qt = blockIdx.x;   // q tile index (0..31)
    const int h  = blockIdx.y;
    const int b  = blockIdx.z;
    const int q0 = qt * 64;
    const float scale = 0.125f;  // 1/sqrt(64)

    const size_t base = (size_t)b * SS * EE + (size_t)h * DD;

    // Load Q tile transposed: Qt[d][r]
    #pragma unroll
    for (int l = 0; l < 4; l++) {
        int idx = tid + l * 256;
        int r = idx >> 4;
        int d4 = (idx & 15) * 4;
        float4 v = *(const float4*)&Qg[base + (size_t)(q0 + r) * EE + d4];
        Qt[d4 + 0][r] = v.x;
        Qt[d4 + 1][r] = v.y;
        Qt[d4 + 2][r] = v.z;
        Qt[d4 + 3][r] = v.w;
    }

    float o[4][4] = {};
    float mrow[4] = {-CUDART_INF_F, -CUDART_INF_F, -CUDART_INF_F, -CUDART_INF_F};
    float lrow[4] = {0.f, 0.f, 0.f, 0.f};

    for (int kt = 0; kt <= qt; kt++) {
        const int k0 = kt * 64;
        __syncthreads();  // protect KtP/Vs from overwrite while still being read

        // Load K tile transposed (Kt[d][c]) and V tile direct (Vs[c][d])
        #pragma unroll
        for (int l = 0; l < 4; l++) {
            int idx = tid + l * 256;
            int r = idx >> 4;
            int d4 = (idx & 15) * 4;
            float4 kv = *(const float4*)&Kg[base + (size_t)(k0 + r) * EE + d4];
            KtP[d4 + 0][r] = kv.x;
            KtP[d4 + 1][r] = kv.y;
            KtP[d4 + 2][r] = kv.z;
            KtP[d4 + 3][r] = kv.w;
            float4 vv = *(const float4*)&Vg[base + (size_t)(k0 + r) * EE + d4];
            *(float4*)&Vs[r][d4] = vv;
        }
        __syncthreads();

        // S = Q @ K^T  (raw dot products)
        float s[4][4] = {};
        #pragma unroll
        for (int d = 0; d < 64; d++) {
            float4 qa = *(const float4*)&Qt[d][ty * 4];
            float4 kb = *(const float4*)&KtP[d][tx * 4];
            float a[4] = {qa.x, qa.y, qa.z, qa.w};
            float c[4] = {kb.x, kb.y, kb.z, kb.w};
            #pragma unroll
            for (int i = 0; i < 4; i++)
                #pragma unroll
                for (int j = 0; j < 4; j++)
                    s[i][j] = fmaf(a[i], c[j], s[i][j]);
        }

        // scale + causal mask
        const bool diag = (kt == qt);
        #pragma unroll
        for (int i = 0; i < 4; i++) {
            int qg = q0 + ty * 4 + i;
            #pragma unroll
            for (int j = 0; j < 4; j++) {
                float t = s[i][j] * scale;
                if (diag && (k0 + tx * 4 + j) > qg) t = -CUDART_INF_F;
                s[i][j] = t;
            }
        }

        // row max over 64 cols (4 local + 16-lane shuffle reduce)
        float rmax[4], rsum[4], mnew[4], alpha[4];
        #pragma unroll
        for (int i = 0; i < 4; i++) {
            float v = fmaxf(fmaxf(s[i][0], s[i][1]), fmaxf(s[i][2], s[i][3]));
            #pragma unroll
            for (int m = 8; m >= 1; m >>= 1)
                v = fmaxf(v, __shfl_xor_sync(0xffffffffu, v, m));
            rmax[i] = v;
            mnew[i] = fmaxf(mrow[i], v);
            alpha[i] = expf(mrow[i] - mnew[i]);  // expf(-inf)=0 on first tile
        }

        // p = exp(s - mnew), row sums
        #pragma unroll
        for (int i = 0; i < 4; i++) {
            float ssum = 0.f;
            #pragma unroll
            for (int j = 0; j < 4; j++) {
                float p = expf(s[i][j] - mnew[i]);  // masked -> exp(-inf)=0
                s[i][j] = p;
                ssum += p;
            }
            #pragma unroll
            for (int m = 8; m >= 1; m >>= 1)
                ssum += __shfl_xor_sync(0xffffffffu, ssum, m);
            rsum[i] = ssum;
        }

        #pragma unroll
        for (int i = 0; i < 4; i++) {
            lrow[i] = lrow[i] * alpha[i] + rsum[i];
            mrow[i] = mnew[i];
            #pragma unroll
            for (int j = 0; j < 4; j++)
                o[i][j] *= alpha[i];
        }

        __syncthreads();  // done reading KtP as K^T

        // store P transposed: Ps[c][r]
        #pragma unroll
        for (int i = 0; i < 4; i++)
            #pragma unroll
            for (int j = 0; j < 4; j++)
                KtP[tx * 4 + j][ty * 4 + i] = s[i][j];
        __syncthreads();

        // O += P @ V
        #pragma unroll
        for (int c = 0; c < 64; c++) {
            float4 pa = *(const float4*)&KtP[c][ty * 4];
            float4 vb = *(const float4*)&Vs[c][tx * 4];
            float a[4] = {pa.x, pa.y, pa.z, pa.w};
            float v[4] = {vb.x, vb.y, vb.z, vb.w};
            #pragma unroll
            for (int i = 0; i < 4; i++)
                #pragma unroll
                for (int j = 0; j < 4; j++)
                    o[i][j] = fmaf(a[i], v[j], o[i][j]);
        }
    }

    // normalize and write ctx[B,S,E]
    #pragma unroll
    for (int i = 0; i < 4; i++) {
        float inv = 1.f / lrow[i];
        float4 w;
        w.x = o[i][0] * inv;
        w.y = o[i][1] * inv;
        w.z = o[i][2] * inv;
        w.w = o[i][3] * inv;
        *(float4*)&ctx[base + (size_t)(q0 + ty * 4 + i) * EE + tx * 4] = w;
    }
}

// ---------------------------------------------------------------------------
// Launch
// ---------------------------------------------------------------------------
extern "C" void kernel_launch(void* const* d_in, const int* in_sizes, int n_in,
                              void* d_out, int out_size)
{
    (void)in_sizes; (void)n_in; (void)out_size;
    const float* x  = (const float*)d_in[0];
    const float* Wq = (const float*)d_in[1];
    const float* bq = (const float*)d_in[2];
    const float* Wk = (const float*)d_in[3];
    const float* bk = (const float*)d_in[4];
    const float* Wv = (const float*)d_in[5];
    const float* bv = (const float*)d_in[6];
    const float* Wo = (const float*)d_in[7];
    const float* bo = (const float*)d_in[8];
    float* out = (float*)d_out;

    float *qp, *kp, *vp, *cp;
    cudaGetSymbolAddress((void**)&qp, g_q);
    cudaGetSymbolAddress((void**)&kp, g_k);
    cudaGetSymbolAddress((void**)&vp, g_v);
    cudaGetSymbolAddress((void**)&cp, g_ctx);

    const int M = BB * SS, N = EE, K = EE;
    dim3 gg(N / 64, M / 64);  // (16, 64)

    sgemm64<<<gg, 256>>>(x, Wq, bq, qp, M, N, K);
    sgemm64<<<gg, 256>>>(x, Wk, bk, kp, M, N, K);
    sgemm64<<<gg, 256>>>(x, Wv, bv, vp, M, N, K);

    const int smem = 3 * 64 * 68 * (int)sizeof(float);  // 52224
    cudaFuncSetAttribute(flash_attn, cudaFuncAttributeMaxDynamicSharedMemorySize, smem);
    flash_attn<<<dim3(SS / 64, HH, BB), 256, smem>>>(qp, kp, vp, cp);

    sgemm64<<<gg, 256>>>(cp, Wo, bo, out, M, N, K);
}

// round 3
// speedup vs baseline: 2.1117x; 2.1117x over previous
#include <cuda_runtime.h>
#include <math_constants.h>
#include <cstdint>

// Problem constants
#define BB 2
#define SS 2048
#define EE 1024
#define HH 16
#define DD 64
// M rows for projections = B*S = 4096

// Scratch (device globals — allocation-free rule)
__device__ float g_q[BB * SS * EE];
__device__ float g_k[BB * SS * EE];
__device__ float g_v[BB * SS * EE];
__device__ float g_ctx[BB * SS * EE];

// ---------------------------------------------------------------------------
// tf32 helpers
// ---------------------------------------------------------------------------
__device__ __forceinline__ float f2tf(float f) {
    uint32_t u;
    asm("cvt.rna.tf32.f32 %0, %1;" : "=r"(u) : "f"(f));
    return __uint_as_float(u);
}

__device__ __forceinline__ void mma_tf32(
    float* c, const uint32_t* a, uint32_t b0, uint32_t b1)
{
    asm volatile(
        "mma.sync.aligned.m16n8k8.row.col.f32.tf32.tf32.f32 "
        "{%0,%1,%2,%3},{%4,%5,%6,%7},{%8,%9},{%0,%1,%2,%3};\n"
        : "+f"(c[0]), "+f"(c[1]), "+f"(c[2]), "+f"(c[3])
        : "r"(a[0]), "r"(a[1]), "r"(a[2]), "r"(a[3]), "r"(b0), "r"(b1));
}

// ---------------------------------------------------------------------------
// tf32 tensor-core SGEMM: C[M,N] = A[M,K] @ W[K,N] + bias
// BM=128, BN=128, BK=16, 256 threads (8 warps as 4x2), warp tile 32x64.
// ---------------------------------------------------------------------------
#define GBM 128
#define GBN 128
#define GBK 16
#define APITCH 20    // 20 mod 32 == 20; stride*row gives distinct-mult-of-4 banks
#define BPITCH 132   // 132 mod 32 == 4 -> conflict-free B frag reads

__global__ __launch_bounds__(256, 2) void sgemm_tf32(
    const float* __restrict__ A, const float* __restrict__ W,
    const float* __restrict__ bias, float* __restrict__ C,
    int M, int N, int K)
{
    __shared__ float As[2][GBM * APITCH];
    __shared__ float Bs[2][GBK * BPITCH];

    const int tid  = threadIdx.x;
    const int lane = tid & 31;
    const int warp = tid >> 5;
    const int gid  = lane >> 2;   // 0..7
    const int tig  = lane & 3;    // 0..3
    const int wm   = warp >> 1;   // 0..3
    const int wn   = warp & 1;    // 0..1
    const int m0   = blockIdx.y * GBM;
    const int n0   = blockIdx.x * GBN;

    // global load assignments
    const int arow = tid >> 1;            // 0..127
    const int akq  = (tid & 1) * 8;       // 0 or 8
    const int brow = tid >> 4;            // 0..15
    const int bcol = (tid & 15) * 8;      // 0..120

    float acc[2][8][4] = {};

    // prologue: load tile 0
    {
        float4 a0 = *(const float4*)&A[(size_t)(m0 + arow) * K + akq];
        float4 a1 = *(const float4*)&A[(size_t)(m0 + arow) * K + akq + 4];
        float* as = &As[0][arow * APITCH + akq];
        as[0] = f2tf(a0.x); as[1] = f2tf(a0.y); as[2] = f2tf(a0.z); as[3] = f2tf(a0.w);
        as[4] = f2tf(a1.x); as[5] = f2tf(a1.y); as[6] = f2tf(a1.z); as[7] = f2tf(a1.w);
        float4 b0 = *(const float4*)&W[(size_t)brow * N + n0 + bcol];
        float4 b1 = *(const float4*)&W[(size_t)brow * N + n0 + bcol + 4];
        float* bs = &Bs[0][brow * BPITCH + bcol];
        bs[0] = f2tf(b0.x); bs[1] = f2tf(b0.y); bs[2] = f2tf(b0.z); bs[3] = f2tf(b0.w);
        bs[4] = f2tf(b1.x); bs[5] = f2tf(b1.y); bs[6] = f2tf(b1.z); bs[7] = f2tf(b1.w);
    }
    __syncthreads();

    int buf = 0;
    for (int kt = 0; kt < K; kt += GBK) {
        const bool has_next = (kt + GBK) < K;
        float4 ra0, ra1, rb0, rb1;
        if (has_next) {
            ra0 = *(const float4*)&A[(size_t)(m0 + arow) * K + kt + GBK + akq];
            ra1 = *(const float4*)&A[(size_t)(m0 + arow) * K + kt + GBK + akq + 4];
            rb0 = *(const float4*)&W[(size_t)(kt + GBK + brow) * N + n0 + bcol];
            rb1 = *(const float4*)&W[(size_t)(kt + GBK + brow) * N + n0 + bcol + 4];
        }

        const float* as = As[buf];
        const float* bs = Bs[buf];
        #pragma unroll
        for (int ks = 0; ks < 2; ks++) {
            uint32_t af[2][4];
            #pragma unroll
            for (int i = 0; i < 2; i++) {
                int mr = wm * 32 + i * 16 + gid;
                af[i][0] = __float_as_uint(as[(mr    ) * APITCH + ks * 8 + tig    ]);
                af[i][1] = __float_as_uint(as[(mr + 8) * APITCH + ks * 8 + tig    ]);
                af[i][2] = __float_as_uint(as[(mr    ) * APITCH + ks * 8 + tig + 4]);
                af[i][3] = __float_as_uint(as[(mr + 8) * APITCH + ks * 8 + tig + 4]);
            }
            #pragma unroll
            for (int j = 0; j < 8; j++) {
                int nc = wn * 64 + j * 8 + gid;
                uint32_t b0 = __float_as_uint(bs[(ks * 8 + tig    ) * BPITCH + nc]);
                uint32_t b1 = __float_as_uint(bs[(ks * 8 + tig + 4) * BPITCH + nc]);
                #pragma unroll
                for (int i = 0; i < 2; i++)
                    mma_tf32(acc[i][j], af[i], b0, b1);
            }
        }

        if (has_next) {
            float* asn = &As[buf ^ 1][arow * APITCH + akq];
            asn[0] = f2tf(ra0.x); asn[1] = f2tf(ra0.y); asn[2] = f2tf(ra0.z); asn[3] = f2tf(ra0.w);
            asn[4] = f2tf(ra1.x); asn[5] = f2tf(ra1.y); asn[6] = f2tf(ra1.z); asn[7] = f2tf(ra1.w);
            float* bsn = &Bs[buf ^ 1][brow * BPITCH + bcol];
            bsn[0] = f2tf(rb0.x); bsn[1] = f2tf(rb0.y); bsn[2] = f2tf(rb0.z); bsn[3] = f2tf(rb0.w);
            bsn[4] = f2tf(rb1.x); bsn[5] = f2tf(rb1.y); bsn[6] = f2tf(rb1.z); bsn[7] = f2tf(rb1.w);
            __syncthreads();
            buf ^= 1;
        }
    }

    // epilogue: bias + store
    #pragma unroll
    for (int i = 0; i < 2; i++) {
        int r = m0 + wm * 32 + i * 16 + gid;
        #pragma unroll
        for (int j = 0; j < 8; j++) {
            int c = n0 + wn * 64 + j * 8 + 2 * tig;
            float2 bb = *(const float2*)&bias[c];
            float2 o0, o1;
            o0.x = acc[i][j][0] + bb.x;
            o0.y = acc[i][j][1] + bb.y;
            o1.x = acc[i][j][2] + bb.x;
            o1.y = acc[i][j][3] + bb.y;
            *(float2*)&C[(size_t)r * N + c]       = o0;
            *(float2*)&C[(size_t)(r + 8) * N + c] = o1;
        }
    }
}

// ---------------------------------------------------------------------------
// tf32 tensor-core causal flash attention.
// CTA: 64 q rows (4 warps x m16). K tile 64. D=64.
// Q pre-scaled by 1/sqrt(D), kept in registers as A-fragments.
// smem: Ks[64][68], Vs[64][68], Ps[64][68]  (tf32-rounded)
// ---------------------------------------------------------------------------
#define KPITCH 68  // 68 mod 32 == 4 -> conflict-free fragment reads

__global__ __launch_bounds__(128) void flash_attn_tc(
    const float* __restrict__ Qg, const float* __restrict__ Kg,
    const float* __restrict__ Vg, float* __restrict__ ctx)
{
    extern __shared__ float sm[];
    float* Ks = sm;                 // [64][KPITCH]
    float* Vs = sm + 64 * KPITCH;   // [64][KPITCH]
    float* Ps = sm + 2 * 64 * KPITCH;

    const int tid  = threadIdx.x;
    const int lane = tid & 31;
    const int warp = tid >> 5;      // 0..3
    const int gid  = lane >> 2;
    const int tig  = lane & 3;
    const int qt   = (int)gridDim.x - 1 - (int)blockIdx.x;  // heavy tiles first
    const int h    = blockIdx.y;
    const int b    = blockIdx.z;
    const int q0   = qt * 64;
    const int wrow = warp * 16;

    const size_t base = (size_t)b * SS * EE + (size_t)h * DD;

    // global staging assignment: 128 threads cover 64 rows x 64 cols
    const int grow = tid >> 1;          // 0..63
    const int ghalf = (tid & 1) * 32;   // 0 or 32

    // ---- stage Q through Ks, pre-scaled, build fragments ----
    {
        const float sc = 0.125f;  // 1/sqrt(64)
        #pragma unroll
        for (int u = 0; u < 8; u++) {
            float4 v = *(const float4*)&Qg[base + (size_t)(q0 + grow) * EE + ghalf + u * 4];
            float* d = &Ks[grow * KPITCH + ghalf + u * 4];
            d[0] = f2tf(v.x * sc); d[1] = f2tf(v.y * sc);
            d[2] = f2tf(v.z * sc); d[3] = f2tf(v.w * sc);
        }
    }
    __syncthreads();

    uint32_t qf[8][4];
    #pragma unroll
    for (int ks = 0; ks < 8; ks++) {
        int r = wrow + gid;
        qf[ks][0] = __float_as_uint(Ks[(r    ) * KPITCH + ks * 8 + tig    ]);
        qf[ks][1] = __float_as_uint(Ks[(r + 8) * KPITCH + ks * 8 + tig    ]);
        qf[ks][2] = __float_as_uint(Ks[(r    ) * KPITCH + ks * 8 + tig + 4]);
        qf[ks][3] = __float_as_uint(Ks[(r + 8) * KPITCH + ks * 8 + tig + 4]);
    }

    float oacc[8][4] = {};
    float m0r = -CUDART_INF_F, m1r = -CUDART_INF_F;
    float l0 = 0.f, l1 = 0.f;
    const int r0g = q0 + wrow + gid;
    const int r1g = r0g + 8;

    for (int kt = 0; kt <= qt; kt++) {
        const int k0 = kt * 64;
        __syncthreads();  // all warps done reading Ks/Vs/Ps

        // stage K, V tiles (tf32)
        #pragma unroll
        for (int u = 0; u < 8; u++) {
            float4 kv = *(const float4*)&Kg[base + (size_t)(k0 + grow) * EE + ghalf + u * 4];
            float* dk = &Ks[grow * KPITCH + ghalf + u * 4];
            dk[0] = f2tf(kv.x); dk[1] = f2tf(kv.y); dk[2] = f2tf(kv.z); dk[3] = f2tf(kv.w);
            float4 vv = *(const float4*)&Vg[base + (size_t)(k0 + grow) * EE + ghalf + u * 4];
            float* dv = &Vs[grow * KPITCH + ghalf + u * 4];
            dv[0] = f2tf(vv.x); dv[1] = f2tf(vv.y); dv[2] = f2tf(vv.z); dv[3] = f2tf(vv.w);
        }
        __syncthreads();

        // S = Q @ K^T : sacc[t] covers keys k0 + t*8..t*8+7
        float sacc[8][4] = {};
        #pragma unroll
        for (int t = 0; t < 8; t++) {
            #pragma unroll
            for (int ks = 0; ks < 8; ks++) {
                uint32_t b0 = __float_as_uint(Ks[(t * 8 + gid) * KPITCH + ks * 8 + tig    ]);
                uint32_t b1 = __float_as_uint(Ks[(t * 8 + gid) * KPITCH + ks * 8 + tig + 4]);
                mma_tf32(sacc[t], qf[ks], b0, b1);
            }
        }

        // causal mask (only diagonal tile)
        if (kt == qt) {
            #pragma unroll
            for (int t = 0; t < 8; t++) {
                int c = k0 + t * 8 + 2 * tig;
                if (c     > r0g) sacc[t][0] = -CUDART_INF_F;
                if (c + 1 > r0g) sacc[t][1] = -CUDART_INF_F;
                if (c     > r1g) sacc[t][2] = -CUDART_INF_F;
                if (c + 1 > r1g) sacc[t][3] = -CUDART_INF_F;
            }
        }

        // online softmax on fragments
        float vm0 = -CUDART_INF_F, vm1 = -CUDART_INF_F;
        #pragma unroll
        for (int t = 0; t < 8; t++) {
            vm0 = fmaxf(vm0, fmaxf(sacc[t][0], sacc[t][1]));
            vm1 = fmaxf(vm1, fmaxf(sacc[t][2], sacc[t][3]));
        }
        vm0 = fmaxf(vm0, __shfl_xor_sync(0xffffffffu, vm0, 1));
        vm0 = fmaxf(vm0, __shfl_xor_sync(0xffffffffu, vm0, 2));
        vm1 = fmaxf(vm1, __shfl_xor_sync(0xffffffffu, vm1, 1));
        vm1 = fmaxf(vm1, __shfl_xor_sync(0xffffffffu, vm1, 2));

        float mn0 = fmaxf(m0r, vm0), mn1 = fmaxf(m1r, vm1);
        float al0 = __expf(m0r - mn0), al1 = __expf(m1r - mn1);

        float sum0 = 0.f, sum1 = 0.f;
        #pragma unroll
        for (int t = 0; t < 8; t++) {
            float p0 = __expf(sacc[t][0] - mn0);
            float p1 = __expf(sacc[t][1] - mn0);
            float p2 = __expf(sacc[t][2] - mn1);
            float p3 = __expf(sacc[t][3] - mn1);
            sacc[t][0] = p0; sacc[t][1] = p1; sacc[t][2] = p2; sacc[t][3] = p3;
            sum0 += p0 + p1;
            sum1 += p2 + p3;
        }
        sum0 += __shfl_xor_sync(0xffffffffu, sum0, 1);
        sum0 += __shfl_xor_sync(0xffffffffu, sum0, 2);
        sum1 += __shfl_xor_sync(0xffffffffu, sum1, 1);
        sum1 += __shfl_xor_sync(0xffffffffu, sum1, 2);

        l0 = l0 * al0 + sum0;  m0r = mn0;
        l1 = l1 * al1 + sum1;  m1r = mn1;
        #pragma unroll
        for (int dt = 0; dt < 8; dt++) {
            oacc[dt][0] *= al0; oacc[dt][1] *= al0;
            oacc[dt][2] *= al1; oacc[dt][3] *= al1;
        }

        // stage P (tf32) per-warp, re-enter as A fragments
        #pragma unroll
        for (int t = 0; t < 8; t++) {
            int pr = wrow + gid;
            Ps[(pr    ) * KPITCH + t * 8 + 2 * tig    ] = f2tf(sacc[t][0]);
            Ps[(pr    ) * KPITCH + t * 8 + 2 * tig + 1] = f2tf(sacc[t][1]);
            Ps[(pr + 8) * KPITCH + t * 8 + 2 * tig    ] = f2tf(sacc[t][2]);
            Ps[(pr + 8) * KPITCH + t * 8 + 2 * tig + 1] = f2tf(sacc[t][3]);
        }
        __syncwarp();

        // O += P @ V
        #pragma unroll
        for (int ks = 0; ks < 8; ks++) {
            int pr = wrow + gid;
            uint32_t af[4];
            af[0] = __float_as_uint(Ps[(pr    ) * KPITCH + ks * 8 + tig    ]);
            af[1] = __float_as_uint(Ps[(pr + 8) * KPITCH + ks * 8 + tig    ]);
            af[2] = __float_as_uint(Ps[(pr    ) * KPITCH + ks * 8 + tig + 4]);
            af[3] = __float_as_uint(Ps[(pr + 8) * KPITCH + ks * 8 + tig + 4]);
            #pragma unroll
            for (int dt = 0; dt < 8; dt++) {
                uint32_t b0 = __float_as_uint(Vs[(ks * 8 + tig    ) * KPITCH + dt * 8 + gid]);
                uint32_t b1 = __float_as_uint(Vs[(ks * 8 + tig + 4) * KPITCH + dt * 8 + gid]);
                mma_tf32(oacc[dt], af, b0, b1);
            }
        }
    }

    // normalize + store ctx
    float inv0 = 1.f / l0, inv1 = 1.f / l1;
    #pragma unroll
    for (int dt = 0; dt < 8; dt++) {
        int c = dt * 8 + 2 * tig;
        float2 w0, w1;
        w0.x = oacc[dt][0] * inv0;  w0.y = oacc[dt][1] * inv0;
        w1.x = oacc[dt][2] * inv1;  w1.y = oacc[dt][3] * inv1;
        *(float2*)&ctx[base + (size_t)r0g * EE + c] = w0;
        *(float2*)&ctx[base + (size_t)r1g * EE + c] = w1;
    }
}

// ---------------------------------------------------------------------------
// Launch
// ---------------------------------------------------------------------------
extern "C" void kernel_launch(void* const* d_in, const int* in_sizes, int n_in,
                              void* d_out, int out_size)
{
    (void)in_sizes; (void)n_in; (void)out_size;
    const float* x  = (const float*)d_in[0];
    const float* Wq = (const float*)d_in[1];
    const float* bq = (const float*)d_in[2];
    const float* Wk = (const float*)d_in[3];
    const float* bk = (const float*)d_in[4];
    const float* Wv = (const float*)d_in[5];
    const float* bv = (const float*)d_in[6];
    const float* Wo = (const float*)d_in[7];
    const float* bo = (const float*)d_in[8];
    float* out = (float*)d_out;

    float *qp, *kp, *vp, *cp;
    cudaGetSymbolAddress((void**)&qp, g_q);
    cudaGetSymbolAddress((void**)&kp, g_k);
    cudaGetSymbolAddress((void**)&vp, g_v);
    cudaGetSymbolAddress((void**)&cp, g_ctx);

    const int M = BB * SS, N = EE, K = EE;
    dim3 gg(N / GBN, M / GBM);  // (8, 32)

    sgemm_tf32<<<gg, 256>>>(x, Wq, bq, qp, M, N, K);
    sgemm_tf32<<<gg, 256>>>(x, Wk, bk, kp, M, N, K);
    sgemm_tf32<<<gg, 256>>>(x, Wv, bv, vp, M, N, K);

    const int smem = 3 * 64 * KPITCH * (int)sizeof(float);  // 52224
    cudaFuncSetAttribute(flash_attn_tc, cudaFuncAttributeMaxDynamicSharedMemorySize, smem);
    flash_attn_tc<<<dim3(SS / 64, HH, BB), 128, smem>>>(qp, kp, vp, cp);

    sgemm_tf32<<<gg, 256>>>(cp, Wo, bo, out, M, N, K);
}